// round 6
// baseline (speedup 1.0000x reference)
#include <cuda_runtime.h>

#define B_TOT 4096
#define T_LEN 512
#define D_IN  5
#define NB    32          // batches per CTA
#define NTHR  512         // 16 warps, 4 per SMSP

// shared memory layout (float offsets); u64 arrays are 8B-aligned
#define OFF_WHH0 0
#define OFF_WIH1 16384
#define OFF_WHH1 32768
#define OFF_H0   49152                 // u64[64*32]  = 4096 floats
#define OFF_H1   (OFF_H0 + 4096)       // u64[64*32]
#define OFF_X    (OFF_H1 + 4096)       // u64[5*32]   = 320 floats
#define SMEM_FLOATS (OFF_X + 320)      // 57,664 floats
#define SMEM_BYTES  (SMEM_FLOATS * 4)  // 230,656 B (R2 proved 230,816 boots)

typedef unsigned long long u64;

union F2U { float2 f; u64 u; };

__device__ __forceinline__ u64 pack2(float lo, float hi) {
    F2U t; t.f = make_float2(lo, hi); return t.u;
}
__device__ __forceinline__ u64 dup2(float x) { return pack2(x, x); }
__device__ __forceinline__ float2 unpk(u64 v) { F2U t; t.u = v; return t.f; }

// packed fp32x2 FMA: a.lo += x.lo*w.lo ; a.hi += x.hi*w.hi
__device__ __forceinline__ void fma2(u64& a, u64 x, u64 w) {
    asm("fma.rn.f32x2 %0, %1, %2, %0;" : "+l"(a) : "l"(x), "l"(w));
}

// MUFU.TANH (validated: rel_err ~7e-7)
__device__ __forceinline__ float tanha(float x) {
    float y; asm("tanh.approx.f32 %0, %1;" : "=f"(y) : "f"(x)); return y;
}
__device__ __forceinline__ float sigf(float x) {
    return fmaf(0.5f, tanha(0.5f * x), 0.5f);
}

__global__ void __launch_bounds__(NTHR, 1)
stocklstm_kernel(const float* __restrict__ x,
                 const float* __restrict__ W_ih0, const float* __restrict__ W_hh0,
                 const float* __restrict__ b_ih0, const float* __restrict__ b_hh0,
                 const float* __restrict__ W_ih1, const float* __restrict__ W_hh1,
                 const float* __restrict__ b_ih1, const float* __restrict__ b_hh1,
                 const float* __restrict__ W1,   const float* __restrict__ b1,
                 const float* __restrict__ W2,   const float* __restrict__ b2,
                 float* __restrict__ out)
{
    extern __shared__ float sm[];
    float* whh0 = sm + OFF_WHH0;
    float* wih1 = sm + OFF_WIH1;
    float* whh1 = sm + OFF_WHH1;
    u64* h0s = (u64*)(sm + OFF_H0);    // h0 duplicated pairs: h0s[k*32+b] = (h,h)
    u64* h1s = (u64*)(sm + OFF_H1);
    u64* x2s = (u64*)(sm + OFF_X);     // x duplicated pairs: x2s[d*32+b]

    const int tid  = threadIdx.x;
    const int lane = tid & 31;
    const int wrp  = tid >> 5;
    // warp covers 8 j-values x 4 batch-groups -> 1-wavefront weight LDS
    const int j  = (lane & 7) | ((wrp & 7) << 3);   // hidden unit 0..63
    const int bg = (lane >> 3) | ((wrp >> 3) << 2); // batch group 0..7
    const int bb = bg * 4;                          // first of 4 batches
    const int B0 = blockIdx.x * NB;

    // ---- stage recurrent/input weights, packed [k][j][4 gates] ----
    for (int idx = tid; idx < 256 * 64; idx += NTHR) {
        int g = idx >> 6, k = idx & 63;          // global row-major [G][64]
        int gi = g >> 6, jj = g & 63;            // gate type, unit
        int dst = (k * 64 + jj) * 4 + gi;
        whh0[dst] = W_hh0[idx];
        wih1[dst] = W_ih1[idx];
        whh1[dst] = W_hh1[idx];
    }
    for (int idx = tid; idx < 64 * 32; idx += NTHR) { h0s[idx] = 0ULL; h1s[idx] = 0ULL; }

    // ---- W_ih0 ([256,5] row-major) lives in registers, gate-paired ----
    u64 wifx[5], wgox[5];
#pragma unroll
    for (int d = 0; d < 5; d++) {
        wifx[d] = pack2(W_ih0[j * 5 + d],         W_ih0[(64 + j) * 5 + d]);
        wgox[d] = pack2(W_ih0[(128 + j) * 5 + d], W_ih0[(192 + j) * 5 + d]);
    }
    // gate-paired bias pre-sums
    const u64 bIF0 = pack2(b_ih0[j] + b_hh0[j],             b_ih0[64 + j] + b_hh0[64 + j]);
    const u64 bGO0 = pack2(b_ih0[128 + j] + b_hh0[128 + j], b_ih0[192 + j] + b_hh0[192 + j]);
    const u64 bIF1 = pack2(b_ih1[j] + b_hh1[j],             b_ih1[64 + j] + b_hh1[64 + j]);
    const u64 bGO1 = pack2(b_ih1[128 + j] + b_hh1[128 + j], b_ih1[192 + j] + b_hh1[192 + j]);

    float c0[4], c1[4];
#pragma unroll
    for (int p = 0; p < 4; p++) { c0[p] = 0.0f; c1[p] = 0.0f; }

    // ---- x staging: threads 0..159 own (batch xbi, feature xd) ----
    const int xbi = tid / 5;
    const int xd  = tid - xbi * 5;
    const float* xptr = x + (size_t)(B0 + xbi) * (T_LEN * D_IN) + xd;
    float xreg = 0.0f;
    if (tid < 160) xreg = xptr[0];

    __syncthreads();

    for (int t = 0; t < T_LEN; t++) {
        if (tid < 160) x2s[xd * 32 + xbi] = dup2(xreg);
        __syncthreads();                    // (A) x[t] staged; prev h1 visible
        if (tid < 160) {
            int tn = (t + 1 < T_LEN) ? t + 1 : t;
            xreg = xptr[tn * D_IN];         // prefetch next step
        }

        // ================= Layer 0 gates =================
        u64 aIF[4], aGO[4];
#pragma unroll
        for (int p = 0; p < 4; p++) { aIF[p] = bIF0; aGO[p] = bGO0; }

#pragma unroll
        for (int d = 0; d < 5; d++) {
            const ulonglong2* xp = (const ulonglong2*)&x2s[d * 32 + bb];
            ulonglong2 xa = xp[0], xb = xp[1];
            fma2(aIF[0], xa.x, wifx[d]); fma2(aGO[0], xa.x, wgox[d]);
            fma2(aIF[1], xa.y, wifx[d]); fma2(aGO[1], xa.y, wgox[d]);
            fma2(aIF[2], xb.x, wifx[d]); fma2(aGO[2], xb.x, wgox[d]);
            fma2(aIF[3], xb.y, wifx[d]); fma2(aGO[3], xb.y, wgox[d]);
        }
#pragma unroll 4
        for (int k = 0; k < 64; k++) {
            ulonglong2 wv = *(const ulonglong2*)&whh0[(k * 64 + j) * 4]; // (wi,wf),(wg,wo)
            const ulonglong2* hp = (const ulonglong2*)&h0s[k * 32 + bb];
            ulonglong2 ha = hp[0], hb = hp[1];
            fma2(aIF[0], ha.x, wv.x); fma2(aGO[0], ha.x, wv.y);
            fma2(aIF[1], ha.y, wv.x); fma2(aGO[1], ha.y, wv.y);
            fma2(aIF[2], hb.x, wv.x); fma2(aGO[2], hb.x, wv.y);
            fma2(aIF[3], hb.y, wv.x); fma2(aGO[3], hb.y, wv.y);
        }
        // pointwise L0 (c in registers)
        float hn[4];
#pragma unroll
        for (int p = 0; p < 4; p++) {
            float2 vif = unpk(aIF[p]), vgo = unpk(aGO[p]);
            float gi = sigf(vif.x), gf = sigf(vif.y);
            float gg = tanha(vgo.x), go = sigf(vgo.y);
            float cc = gf * c0[p] + gi * gg;
            c0[p] = cc;
            hn[p] = go * tanha(cc);
        }
        __syncthreads();                    // (B) everyone done reading old h0
        {
            ulonglong2 s0 = { dup2(hn[0]), dup2(hn[1]) };
            ulonglong2 s1 = { dup2(hn[2]), dup2(hn[3]) };
            *(ulonglong2*)&h0s[j * 32 + bb]     = s0;
            *(ulonglong2*)&h0s[j * 32 + bb + 2] = s1;
        }

        // ================= Layer 1: recurrent part (old h1) =================
#pragma unroll
        for (int p = 0; p < 4; p++) { aIF[p] = bIF1; aGO[p] = bGO1; }
#pragma unroll 4
        for (int k = 0; k < 64; k++) {
            ulonglong2 wv = *(const ulonglong2*)&whh1[(k * 64 + j) * 4];
            const ulonglong2* hp = (const ulonglong2*)&h1s[k * 32 + bb];
            ulonglong2 ha = hp[0], hb = hp[1];
            fma2(aIF[0], ha.x, wv.x); fma2(aGO[0], ha.x, wv.y);
            fma2(aIF[1], ha.y, wv.x); fma2(aGO[1], ha.y, wv.y);
            fma2(aIF[2], hb.x, wv.x); fma2(aGO[2], hb.x, wv.y);
            fma2(aIF[3], hb.y, wv.x); fma2(aGO[3], hb.y, wv.y);
        }
        __syncthreads();                    // (C) new h0 visible; old-h1 reads done

        // ================= Layer 1: input part (new h0) =================
#pragma unroll 4
        for (int k = 0; k < 64; k++) {
            ulonglong2 wv = *(const ulonglong2*)&wih1[(k * 64 + j) * 4];
            const ulonglong2* hp = (const ulonglong2*)&h0s[k * 32 + bb];
            ulonglong2 ha = hp[0], hb = hp[1];
            fma2(aIF[0], ha.x, wv.x); fma2(aGO[0], ha.x, wv.y);
            fma2(aIF[1], ha.y, wv.x); fma2(aGO[1], ha.y, wv.y);
            fma2(aIF[2], hb.x, wv.x); fma2(aGO[2], hb.x, wv.y);
            fma2(aIF[3], hb.y, wv.x); fma2(aGO[3], hb.y, wv.y);
        }
        // pointwise L1
#pragma unroll
        for (int p = 0; p < 4; p++) {
            float2 vif = unpk(aIF[p]), vgo = unpk(aGO[p]);
            float gi = sigf(vif.x), gf = sigf(vif.y);
            float gg = tanha(vgo.x), go = sigf(vgo.y);
            float cc = gf * c1[p] + gi * gg;
            c1[p] = cc;
            hn[p] = go * tanha(cc);
        }
        {
            ulonglong2 s0 = { dup2(hn[0]), dup2(hn[1]) };
            ulonglong2 s1 = { dup2(hn[2]), dup2(hn[3]) };
            *(ulonglong2*)&h1s[j * 32 + bb]     = s0;
            *(ulonglong2*)&h1s[j * 32 + bb + 2] = s1;
        }
        // h1 visibility for next iteration guaranteed by sync (A)
    }
    __syncthreads();

    // ================= MLP head: out = W2 @ relu(W1 @ h2 + b1) + b2 =========
    if (tid < NB) {
        const float* h1f = (const float*)h1s;  // duplicated pairs; take .lo
        float acc = b2[0];
#pragma unroll 1
        for (int u = 0; u < 32; u++) {
            float s = b1[u];
            const float* wr = W1 + u * 64;
#pragma unroll
            for (int k = 0; k < 64; k++) s += wr[k] * h1f[(k * 32 + tid) * 2];
            acc += W2[u] * fmaxf(s, 0.0f);
        }
        out[B0 + tid] = acc;
    }
}

extern "C" void kernel_launch(void* const* d_in, const int* in_sizes, int n_in,
                              void* d_out, int out_size)
{
    const float* x    = (const float*)d_in[0];
    const float* Wih0 = (const float*)d_in[1];
    const float* Whh0 = (const float*)d_in[2];
    const float* bih0 = (const float*)d_in[3];
    const float* bhh0 = (const float*)d_in[4];
    const float* Wih1 = (const float*)d_in[5];
    const float* Whh1 = (const float*)d_in[6];
    const float* bih1 = (const float*)d_in[7];
    const float* bhh1 = (const float*)d_in[8];
    const float* W1   = (const float*)d_in[9];
    const float* b1   = (const float*)d_in[10];
    const float* W2   = (const float*)d_in[11];
    const float* b2   = (const float*)d_in[12];
    float* out = (float*)d_out;

    cudaFuncSetAttribute(stocklstm_kernel,
                         cudaFuncAttributeMaxDynamicSharedMemorySize, SMEM_BYTES);
    stocklstm_kernel<<<B_TOT / NB, NTHR, SMEM_BYTES>>>(
        x, Wih0, Whh0, bih0, bhh0, Wih1, Whh1, bih1, bhh1, W1, b1, W2, b2, out);
}

// round 7
// speedup vs baseline: 1.5540x; 1.5540x over previous
#include <cuda_runtime.h>

#define B_TOT 4096
#define T_LEN 512
#define D_IN  5
#define NB    32          // batches per CTA
#define NTHR  512         // 16 warps, 4/SMSP; k-split inside each warp
#define HS    36          // padded row stride (floats) for h/x state

// shared memory layout (float offsets) — identical to the proven R5 layout
#define OFF_WHH0 0
#define OFF_WIH1 16384
#define OFF_WHH1 32768
#define OFF_WIH0 49152                 // 5*64*4 = 1280
#define OFF_H0   (49152 + 1280)        // 64*36 = 2304
#define OFF_H1   (OFF_H0 + 2304)
#define OFF_X    (OFF_H1 + 2304)       // 5*36 = 180
#define SMEM_FLOATS (OFF_X + 180)
#define SMEM_BYTES  (SMEM_FLOATS * 4)  // 220,880 B

typedef unsigned long long u64;

union F2U { float2 f; u64 u; };

__device__ __forceinline__ u64 dup2(float x) {
    F2U t; t.f = make_float2(x, x); return t.u;
}
__device__ __forceinline__ float2 unpk(u64 v) { F2U t; t.u = v; return t.f; }

__device__ __forceinline__ void fma2(u64& a, u64 x, u64 w) {
    asm("fma.rn.f32x2 %0, %1, %2, %0;" : "+l"(a) : "l"(x), "l"(w));
}
__device__ __forceinline__ u64 add2(u64 a, u64 b) {
    u64 r; asm("add.rn.f32x2 %0, %1, %2;" : "=l"(r) : "l"(a), "l"(b)); return r;
}
__device__ __forceinline__ u64 sx16(u64 v) {
    return __shfl_xor_sync(0xFFFFFFFFu, v, 16);
}

// MUFU.TANH (validated: rel_err ~7e-7)
__device__ __forceinline__ float tanha(float x) {
    float y; asm("tanh.approx.f32 %0, %1;" : "=f"(y) : "f"(x)); return y;
}
__device__ __forceinline__ float sigf(float x) {
    return fmaf(0.5f, tanha(0.5f * x), 0.5f);
}

__global__ void __launch_bounds__(NTHR, 1)
stocklstm_kernel(const float* __restrict__ x,
                 const float* __restrict__ W_ih0, const float* __restrict__ W_hh0,
                 const float* __restrict__ b_ih0, const float* __restrict__ b_hh0,
                 const float* __restrict__ W_ih1, const float* __restrict__ W_hh1,
                 const float* __restrict__ b_ih1, const float* __restrict__ b_hh1,
                 const float* __restrict__ W1,   const float* __restrict__ b1,
                 const float* __restrict__ W2,   const float* __restrict__ b2,
                 float* __restrict__ out)
{
    extern __shared__ float sm[];
    float* whh0 = sm + OFF_WHH0;
    float* wih1 = sm + OFF_WIH1;
    float* whh1 = sm + OFF_WHH1;
    float* wih0 = sm + OFF_WIH0;
    float* h0s  = sm + OFF_H0;
    float* h1s  = sm + OFF_H1;
    float* xs   = sm + OFF_X;

    const int tid  = threadIdx.x;
    const int lane = tid & 31;
    const int wid  = tid >> 5;
    const int kh   = lane >> 4;                 // k-half 0/1
    const int ji   = lane & 15;
    const int j    = ((wid >> 2) << 4) | ji;    // hidden unit 0..63
    const int bg   = wid & 3;                   // batch group 0..3
    const int bb   = bg * 8;                    // 8 batches per warp-group
    const int qb   = bb + kh * 4;               // 4 batches owned for pointwise
    const int kb   = kh * 32;                   // k range [kb, kb+32)
    const int B0   = blockIdx.x * NB;

    // ---- stage weights, packed [k][j][4 gates] for LDS.128 ----
    for (int idx = tid; idx < 256 * 64; idx += NTHR) {
        int g = idx >> 6, k = idx & 63;          // global row-major [G][64]
        int gi = g >> 6, jj = g & 63;            // gate type, unit
        int dst = (k * 64 + jj) * 4 + gi;
        whh0[dst] = W_hh0[idx];
        wih1[dst] = W_ih1[idx];
        whh1[dst] = W_hh1[idx];
    }
    for (int idx = tid; idx < 256 * 5; idx += NTHR) {
        int g = idx / 5, d = idx - 5 * g;
        wih0[(d * 64 + (g & 63)) * 4 + (g >> 6)] = W_ih0[idx];
    }
    for (int idx = tid; idx < 64 * HS; idx += NTHR) { h0s[idx] = 0.0f; h1s[idx] = 0.0f; }

    // biases as float4 (i,f,g,o); dup'd at accumulator init each step
    const float4 bL0 = make_float4(b_ih0[j] + b_hh0[j],
                                   b_ih0[64 + j]  + b_hh0[64 + j],
                                   b_ih0[128 + j] + b_hh0[128 + j],
                                   b_ih0[192 + j] + b_hh0[192 + j]);
    const float4 bL1 = make_float4(b_ih1[j] + b_hh1[j],
                                   b_ih1[64 + j]  + b_hh1[64 + j],
                                   b_ih1[128 + j] + b_hh1[128 + j],
                                   b_ih1[192 + j] + b_hh1[192 + j]);

    float c0[4], c1[4];
#pragma unroll
    for (int p = 0; p < 4; p++) { c0[p] = 0.0f; c1[p] = 0.0f; }

    // ---- x staging: threads 0..159 own (batch xbi, feature xd) ----
    const int xbi = tid / 5;
    const int xd  = tid - xbi * 5;
    const float* xptr = x + (size_t)(B0 + xbi) * (T_LEN * D_IN) + xd;
    float xreg = 0.0f;
    if (tid < 160) xreg = xptr[0];

    __syncthreads();

    for (int t = 0; t < T_LEN; t++) {
        if (tid < 160) xs[xd * HS + xbi] = xreg;
        __syncthreads();                    // (A) x[t] staged; prev h1 visible
        if (tid < 160) {
            int tn = (t + 1 < T_LEN) ? t + 1 : t;
            xreg = xptr[tn * D_IN];
        }

        // ================= Layer 0 gates (partial: this k-half) ===========
        u64 aI[4], aF[4], aG[4], aO[4];
        {
            u64 i0 = kh ? 0ULL : dup2(bL0.x);
            u64 f0 = kh ? 0ULL : dup2(bL0.y);
            u64 g0 = kh ? 0ULL : dup2(bL0.z);
            u64 o0 = kh ? 0ULL : dup2(bL0.w);
#pragma unroll
            for (int p = 0; p < 4; p++) { aI[p] = i0; aF[p] = f0; aG[p] = g0; aO[p] = o0; }
        }

        // x contribution: kh==0 lanes only (avoids double count)
        if (kh == 0) {
#pragma unroll
            for (int d = 0; d < 5; d++) {
                float4 w = *(const float4*)&wih0[(d * 64 + j) * 4];
                u64 wi = dup2(w.x), wf = dup2(w.y), wg = dup2(w.z), wo = dup2(w.w);
                const ulonglong2* xp = (const ulonglong2*)&xs[d * HS + bb];
                ulonglong2 xa = xp[0], xb = xp[1];
                fma2(aI[0], xa.x, wi); fma2(aI[1], xa.y, wi); fma2(aI[2], xb.x, wi); fma2(aI[3], xb.y, wi);
                fma2(aF[0], xa.x, wf); fma2(aF[1], xa.y, wf); fma2(aF[2], xb.x, wf); fma2(aF[3], xb.y, wf);
                fma2(aG[0], xa.x, wg); fma2(aG[1], xa.y, wg); fma2(aG[2], xb.x, wg); fma2(aG[3], xb.y, wg);
                fma2(aO[0], xa.x, wo); fma2(aO[1], xa.y, wo); fma2(aO[2], xb.x, wo); fma2(aO[3], xb.y, wo);
            }
        }
#pragma unroll 4
        for (int ki = 0; ki < 32; ki++) {
            int k = kb + ki;
            float4 w = *(const float4*)&whh0[(k * 64 + j) * 4];
            u64 wi = dup2(w.x), wf = dup2(w.y), wg = dup2(w.z), wo = dup2(w.w);
            const ulonglong2* hp = (const ulonglong2*)&h0s[k * HS + bb];
            ulonglong2 ha = hp[0], hb = hp[1];
            fma2(aI[0], ha.x, wi); fma2(aI[1], ha.y, wi); fma2(aI[2], hb.x, wi); fma2(aI[3], hb.y, wi);
            fma2(aF[0], ha.x, wf); fma2(aF[1], ha.y, wf); fma2(aF[2], hb.x, wf); fma2(aF[3], hb.y, wf);
            fma2(aG[0], ha.x, wg); fma2(aG[1], ha.y, wg); fma2(aG[2], hb.x, wg); fma2(aG[3], hb.y, wg);
            fma2(aO[0], ha.x, wo); fma2(aO[1], ha.y, wo); fma2(aO[2], hb.x, wo); fma2(aO[3], hb.y, wo);
        }
        // butterfly combine k-halves (both lanes get full sums)
#pragma unroll
        for (int p = 0; p < 4; p++) {
            aI[p] = add2(aI[p], sx16(aI[p]));
            aF[p] = add2(aF[p], sx16(aF[p]));
            aG[p] = add2(aG[p], sx16(aG[p]));
            aO[p] = add2(aO[p], sx16(aO[p]));
        }
        // each lane-half keeps its 4 batches (pairs kh*2, kh*2+1)
        {
            u64 gI0 = kh ? aI[2] : aI[0], gI1 = kh ? aI[3] : aI[1];
            u64 gF0 = kh ? aF[2] : aF[0], gF1 = kh ? aF[3] : aF[1];
            u64 gG0 = kh ? aG[2] : aG[0], gG1 = kh ? aG[3] : aG[1];
            u64 gO0 = kh ? aO[2] : aO[0], gO1 = kh ? aO[3] : aO[1];
            float2 vi0 = unpk(gI0), vi1 = unpk(gI1);
            float2 vf0 = unpk(gF0), vf1 = unpk(gF1);
            float2 vg0 = unpk(gG0), vg1 = unpk(gG1);
            float2 vo0 = unpk(gO0), vo1 = unpk(gO1);
            float ca0 = sigf(vf0.x) * c0[0] + sigf(vi0.x) * tanha(vg0.x);
            float ca1 = sigf(vf0.y) * c0[1] + sigf(vi0.y) * tanha(vg0.y);
            float ca2 = sigf(vf1.x) * c0[2] + sigf(vi1.x) * tanha(vg1.x);
            float ca3 = sigf(vf1.y) * c0[3] + sigf(vi1.y) * tanha(vg1.y);
            c0[0] = ca0; c0[1] = ca1; c0[2] = ca2; c0[3] = ca3;
            float h0n0 = sigf(vo0.x) * tanha(ca0);
            float h0n1 = sigf(vo0.y) * tanha(ca1);
            float h0n2 = sigf(vo1.x) * tanha(ca2);
            float h0n3 = sigf(vo1.y) * tanha(ca3);
            __syncthreads();                // (B) all reads of old h0 done
            *(float4*)&h0s[j * HS + qb] = make_float4(h0n0, h0n1, h0n2, h0n3);
        }

        // ===== Layer 1: recurrent part (old h1), this k-half =====
        {
            u64 i0 = kh ? 0ULL : dup2(bL1.x);
            u64 f0 = kh ? 0ULL : dup2(bL1.y);
            u64 g0 = kh ? 0ULL : dup2(bL1.z);
            u64 o0 = kh ? 0ULL : dup2(bL1.w);
#pragma unroll
            for (int p = 0; p < 4; p++) { aI[p] = i0; aF[p] = f0; aG[p] = g0; aO[p] = o0; }
        }
#pragma unroll 4
        for (int ki = 0; ki < 32; ki++) {
            int k = kb + ki;
            float4 w = *(const float4*)&whh1[(k * 64 + j) * 4];
            u64 wi = dup2(w.x), wf = dup2(w.y), wg = dup2(w.z), wo = dup2(w.w);
            const ulonglong2* hp = (const ulonglong2*)&h1s[k * HS + bb];
            ulonglong2 ha = hp[0], hb = hp[1];
            fma2(aI[0], ha.x, wi); fma2(aI[1], ha.y, wi); fma2(aI[2], hb.x, wi); fma2(aI[3], hb.y, wi);
            fma2(aF[0], ha.x, wf); fma2(aF[1], ha.y, wf); fma2(aF[2], hb.x, wf); fma2(aF[3], hb.y, wf);
            fma2(aG[0], ha.x, wg); fma2(aG[1], ha.y, wg); fma2(aG[2], hb.x, wg); fma2(aG[3], hb.y, wg);
            fma2(aO[0], ha.x, wo); fma2(aO[1], ha.y, wo); fma2(aO[2], hb.x, wo); fma2(aO[3], hb.y, wo);
        }
        __syncthreads();                    // (C) new h0 visible; old-h1 reads done

        // ===== Layer 1: input part (new h0), this k-half =====
#pragma unroll 4
        for (int ki = 0; ki < 32; ki++) {
            int k = kb + ki;
            float4 w = *(const float4*)&wih1[(k * 64 + j) * 4];
            u64 wi = dup2(w.x), wf = dup2(w.y), wg = dup2(w.z), wo = dup2(w.w);
            const ulonglong2* hp = (const ulonglong2*)&h0s[k * HS + bb];
            ulonglong2 ha = hp[0], hb = hp[1];
            fma2(aI[0], ha.x, wi); fma2(aI[1], ha.y, wi); fma2(aI[2], hb.x, wi); fma2(aI[3], hb.y, wi);
            fma2(aF[0], ha.x, wf); fma2(aF[1], ha.y, wf); fma2(aF[2], hb.x, wf); fma2(aF[3], hb.y, wf);
            fma2(aG[0], ha.x, wg); fma2(aG[1], ha.y, wg); fma2(aG[2], hb.x, wg); fma2(aG[3], hb.y, wg);
            fma2(aO[0], ha.x, wo); fma2(aO[1], ha.y, wo); fma2(aO[2], hb.x, wo); fma2(aO[3], hb.y, wo);
        }
        // butterfly combine k-halves
#pragma unroll
        for (int p = 0; p < 4; p++) {
            aI[p] = add2(aI[p], sx16(aI[p]));
            aF[p] = add2(aF[p], sx16(aF[p]));
            aG[p] = add2(aG[p], sx16(aG[p]));
            aO[p] = add2(aO[p], sx16(aO[p]));
        }
        {
            u64 gI0 = kh ? aI[2] : aI[0], gI1 = kh ? aI[3] : aI[1];
            u64 gF0 = kh ? aF[2] : aF[0], gF1 = kh ? aF[3] : aF[1];
            u64 gG0 = kh ? aG[2] : aG[0], gG1 = kh ? aG[3] : aG[1];
            u64 gO0 = kh ? aO[2] : aO[0], gO1 = kh ? aO[3] : aO[1];
            float2 vi0 = unpk(gI0), vi1 = unpk(gI1);
            float2 vf0 = unpk(gF0), vf1 = unpk(gF1);
            float2 vg0 = unpk(gG0), vg1 = unpk(gG1);
            float2 vo0 = unpk(gO0), vo1 = unpk(gO1);
            float ca0 = sigf(vf0.x) * c1[0] + sigf(vi0.x) * tanha(vg0.x);
            float ca1 = sigf(vf0.y) * c1[1] + sigf(vi0.y) * tanha(vg0.y);
            float ca2 = sigf(vf1.x) * c1[2] + sigf(vi1.x) * tanha(vg1.x);
            float ca3 = sigf(vf1.y) * c1[3] + sigf(vi1.y) * tanha(vg1.y);
            c1[0] = ca0; c1[1] = ca1; c1[2] = ca2; c1[3] = ca3;
            float h1n0 = sigf(vo0.x) * tanha(ca0);
            float h1n1 = sigf(vo0.y) * tanha(ca1);
            float h1n2 = sigf(vo1.x) * tanha(ca2);
            float h1n3 = sigf(vo1.y) * tanha(ca3);
            *(float4*)&h1s[j * HS + qb] = make_float4(h1n0, h1n1, h1n2, h1n3);
        }
        // h1 visibility for next iteration guaranteed by sync (A)
    }
    __syncthreads();

    // ================= MLP head: out = W2 @ relu(W1 @ h2 + b1) + b2 =========
    if (tid < NB) {
        float acc = b2[0];
#pragma unroll 1
        for (int u = 0; u < 32; u++) {
            float s = b1[u];
            const float* wr = W1 + u * 64;
#pragma unroll
            for (int k = 0; k < 64; k++) s += wr[k] * h1s[k * HS + tid];
            acc += W2[u] * fmaxf(s, 0.0f);
        }
        out[B0 + tid] = acc;
    }
}

extern "C" void kernel_launch(void* const* d_in, const int* in_sizes, int n_in,
                              void* d_out, int out_size)
{
    const float* x    = (const float*)d_in[0];
    const float* Wih0 = (const float*)d_in[1];
    const float* Whh0 = (const float*)d_in[2];
    const float* bih0 = (const float*)d_in[3];
    const float* bhh0 = (const float*)d_in[4];
    const float* Wih1 = (const float*)d_in[5];
    const float* Whh1 = (const float*)d_in[6];
    const float* bih1 = (const float*)d_in[7];
    const float* bhh1 = (const float*)d_in[8];
    const float* W1   = (const float*)d_in[9];
    const float* b1   = (const float*)d_in[10];
    const float* W2   = (const float*)d_in[11];
    const float* b2   = (const float*)d_in[12];
    float* out = (float*)d_out;

    cudaFuncSetAttribute(stocklstm_kernel,
                         cudaFuncAttributeMaxDynamicSharedMemorySize, SMEM_BYTES);
    stocklstm_kernel<<<B_TOT / NB, NTHR, SMEM_BYTES>>>(
        x, Wih0, Whh0, bih0, bhh0, Wih1, Whh1, bih1, bhh1, W1, b1, W2, b2, out);
}

// round 8
// speedup vs baseline: 1.6909x; 1.0881x over previous
#include <cuda_runtime.h>

#define B_TOT 4096
#define T_LEN 512
#define D_IN  5
#define NB    32          // batches per CTA
#define NTHR  512         // warps 0-7: layer0, warps 8-15: layer1
#define HS    36          // padded row stride (floats) for h/x state

// shared memory layout (float offsets)
#define OFF_WHH0 0
#define OFF_WIH1 16384
#define OFF_WHH1 32768
#define OFF_WIH0 49152                 // 5*64*4 = 1280
#define OFF_B0A  (49152 + 1280)        // h0 buffer 0: 64*36 = 2304
#define OFF_B0B  (OFF_B0A + 2304)      // h0 buffer 1
#define OFF_H1   (OFF_B0B + 2304)
#define OFF_XA   (OFF_H1 + 2304)       // 5*36 = 180
#define OFF_XB   (OFF_XA + 180)
#define SMEM_FLOATS (OFF_XB + 180)     // 57,704 floats
#define SMEM_BYTES  (SMEM_FLOATS * 4)  // 230,816 B (boot-proven in R2)

// named barriers
#define BAR_READY0 1
#define BAR_READY1 2
#define BAR_FREE0  3
#define BAR_FREE1  4
#define BAR_L1INT  7

#define BSYNC(id, cnt) asm volatile("bar.sync %0, %1;" :: "n"(id), "n"(cnt) : "memory")
#define BARRV(id, cnt) asm volatile("bar.arrive %0, %1;" :: "n"(id), "n"(cnt) : "memory")

typedef unsigned long long u64;

union F2U { float2 f; u64 u; };

__device__ __forceinline__ u64 dup2(float x) {
    F2U t; t.f = make_float2(x, x); return t.u;
}
__device__ __forceinline__ float2 unpk(u64 v) { F2U t; t.u = v; return t.f; }

__device__ __forceinline__ void fma2(u64& a, u64 x, u64 w) {
    asm("fma.rn.f32x2 %0, %1, %2, %0;" : "+l"(a) : "l"(x), "l"(w));
}

// MUFU.TANH (validated: rel_err ~7e-7)
__device__ __forceinline__ float tanha(float x) {
    float y; asm("tanh.approx.f32 %0, %1;" : "=f"(y) : "f"(x)); return y;
}
__device__ __forceinline__ float sigf(float x) {
    return fmaf(0.5f, tanha(0.5f * x), 0.5f);
}

// one 64-k gate GEMV accumulation pass (R5 inner loop)
__device__ __forceinline__ void gemv64(const float* __restrict__ W,
                                       const float* __restrict__ hsrc,
                                       int j, int bb,
                                       u64* aI, u64* aF, u64* aG, u64* aO)
{
#pragma unroll 4
    for (int k = 0; k < 64; k++) {
        float4 w = *(const float4*)&W[(k * 64 + j) * 4];
        u64 wi = dup2(w.x), wf = dup2(w.y), wg = dup2(w.z), wo = dup2(w.w);
        const ulonglong2* hp = (const ulonglong2*)&hsrc[k * HS + bb];
        ulonglong2 ha = hp[0], hb = hp[1];
        fma2(aI[0], ha.x, wi); fma2(aI[1], ha.y, wi); fma2(aI[2], hb.x, wi); fma2(aI[3], hb.y, wi);
        fma2(aF[0], ha.x, wf); fma2(aF[1], ha.y, wf); fma2(aF[2], hb.x, wf); fma2(aF[3], hb.y, wf);
        fma2(aG[0], ha.x, wg); fma2(aG[1], ha.y, wg); fma2(aG[2], hb.x, wg); fma2(aG[3], hb.y, wg);
        fma2(aO[0], ha.x, wo); fma2(aO[1], ha.y, wo); fma2(aO[2], hb.x, wo); fma2(aO[3], hb.y, wo);
    }
}

__device__ __forceinline__ void pointwise(const u64* aI, const u64* aF,
                                          const u64* aG, const u64* aO,
                                          float* c, float* hn)
{
#pragma unroll
    for (int p = 0; p < 4; p++) {
        float2 vi = unpk(aI[p]), vf = unpk(aF[p]), vg = unpk(aG[p]), vo = unpk(aO[p]);
        float ca = sigf(vf.x) * c[2 * p]     + sigf(vi.x) * tanha(vg.x);
        float cb = sigf(vf.y) * c[2 * p + 1] + sigf(vi.y) * tanha(vg.y);
        c[2 * p] = ca; c[2 * p + 1] = cb;
        hn[2 * p]     = sigf(vo.x) * tanha(ca);
        hn[2 * p + 1] = sigf(vo.y) * tanha(cb);
    }
}

__global__ void __launch_bounds__(NTHR, 1)
stocklstm_kernel(const float* __restrict__ x,
                 const float* __restrict__ W_ih0, const float* __restrict__ W_hh0,
                 const float* __restrict__ b_ih0, const float* __restrict__ b_hh0,
                 const float* __restrict__ W_ih1, const float* __restrict__ W_hh1,
                 const float* __restrict__ b_ih1, const float* __restrict__ b_hh1,
                 const float* __restrict__ W1,   const float* __restrict__ b1,
                 const float* __restrict__ W2,   const float* __restrict__ b2,
                 float* __restrict__ out)
{
    extern __shared__ float sm[];
    float* whh0 = sm + OFF_WHH0;
    float* wih1 = sm + OFF_WIH1;
    float* whh1 = sm + OFF_WHH1;
    float* wih0 = sm + OFF_WIH0;
    float* bufA = sm + OFF_B0A;
    float* bufB = sm + OFF_B0B;
    float* h1s  = sm + OFF_H1;
    float* xsA  = sm + OFF_XA;
    float* xsB  = sm + OFF_XB;

    const int tid = threadIdx.x;
    const int g   = tid & 255;  // tid within group
    const int j   = g & 63;     // hidden unit
    const int bb  = (g >> 6) * 8;
    const int B0  = blockIdx.x * NB;

    // ---- stage weights, packed [k][j][4 gates] ----
    for (int idx = tid; idx < 256 * 64; idx += NTHR) {
        int gg = idx >> 6, k = idx & 63;
        int gi = gg >> 6, jj = gg & 63;
        int dst = (k * 64 + jj) * 4 + gi;
        whh0[dst] = W_hh0[idx];
        wih1[dst] = W_ih1[idx];
        whh1[dst] = W_hh1[idx];
    }
    for (int idx = tid; idx < 256 * 5; idx += NTHR) {
        int gg = idx / 5, d = idx - 5 * gg;
        wih0[(d * 64 + (gg & 63)) * 4 + (gg >> 6)] = W_ih0[idx];
    }
    for (int idx = tid; idx < 64 * HS; idx += NTHR) {
        bufA[idx] = 0.0f; bufB[idx] = 0.0f; h1s[idx] = 0.0f;
    }
    __syncthreads();   // weights + zeroed state visible to all

    if (tid < 256) {
        // ===================== LAYER 0 GROUP =====================
        const u64 bi0 = dup2(b_ih0[j]       + b_hh0[j]);
        const u64 bf0 = dup2(b_ih0[64 + j]  + b_hh0[64 + j]);
        const u64 bg0 = dup2(b_ih0[128 + j] + b_hh0[128 + j]);
        const u64 bo0 = dup2(b_ih0[192 + j] + b_hh0[192 + j]);
        float c0[8];
#pragma unroll
        for (int p = 0; p < 8; p++) c0[p] = 0.0f;

        // x staging (threads 0..159)
        const int xbi = tid / 5;
        const int xd  = tid - xbi * 5;
        const float* xptr = x + (size_t)(B0 + xbi) * (T_LEN * D_IN) + xd;
        float xreg = 0.0f;
        if (tid < 160) {
            xsA[xd * HS + xbi] = xptr[0];   // stage x[0]
            xreg = xptr[D_IN];              // prefetch x[1]
        }
        // make x[0] visible to all L0 threads: the first free-sync below
        // (rendezvous of all L0 threads) orders these writes.

        for (int t = 0; t < T_LEN; t++) {
            const int p = t & 1;
            float* bw = p ? bufB : bufA;        // write h0[t]
            const float* br = p ? bufA : bufB;  // read h0[t-1]
            const float* xc = p ? xsB : xsA;

            if (p) { BSYNC(BAR_FREE1, NTHR); } else { BSYNC(BAR_FREE0, NTHR); }

            u64 aI[4], aF[4], aG[4], aO[4];
#pragma unroll
            for (int q = 0; q < 4; q++) { aI[q] = bi0; aF[q] = bf0; aG[q] = bg0; aO[q] = bo0; }

#pragma unroll
            for (int d = 0; d < 5; d++) {
                float4 w = *(const float4*)&wih0[(d * 64 + j) * 4];
                u64 wi = dup2(w.x), wf = dup2(w.y), wg = dup2(w.z), wo = dup2(w.w);
                const ulonglong2* xp = (const ulonglong2*)&xc[d * HS + bb];
                ulonglong2 xa = xp[0], xb = xp[1];
                fma2(aI[0], xa.x, wi); fma2(aI[1], xa.y, wi); fma2(aI[2], xb.x, wi); fma2(aI[3], xb.y, wi);
                fma2(aF[0], xa.x, wf); fma2(aF[1], xa.y, wf); fma2(aF[2], xb.x, wf); fma2(aF[3], xb.y, wf);
                fma2(aG[0], xa.x, wg); fma2(aG[1], xa.y, wg); fma2(aG[2], xb.x, wg); fma2(aG[3], xb.y, wg);
                fma2(aO[0], xa.x, wo); fma2(aO[1], xa.y, wo); fma2(aO[2], xb.x, wo); fma2(aO[3], xb.y, wo);
            }
            gemv64(whh0, br, j, bb, aI, aF, aG, aO);

            float hn[8];
            pointwise(aI, aF, aG, aO, c0, hn);
            *(float4*)&bw[j * HS + bb]     = make_float4(hn[0], hn[1], hn[2], hn[3]);
            *(float4*)&bw[j * HS + bb + 4] = make_float4(hn[4], hn[5], hn[6], hn[7]);

            if (p) { BARRV(BAR_READY1, NTHR); } else { BARRV(BAR_READY0, NTHR); }

            // stage x[t+1] into the other parity buffer; prefetch x[t+2]
            if (tid < 160) {
                float* xw = p ? xsA : xsB;
                xw[xd * HS + xbi] = xreg;
                int tn = (t + 2 < T_LEN) ? t + 2 : T_LEN - 1;
                xreg = xptr[tn * D_IN];
            }
        }
    } else {
        // ===================== LAYER 1 GROUP =====================
        const u64 bi1 = dup2(b_ih1[j]       + b_hh1[j]);
        const u64 bf1 = dup2(b_ih1[64 + j]  + b_hh1[64 + j]);
        const u64 bg1 = dup2(b_ih1[128 + j] + b_hh1[128 + j]);
        const u64 bo1 = dup2(b_ih1[192 + j] + b_hh1[192 + j]);
        float c1[8];
#pragma unroll
        for (int p = 0; p < 8; p++) c1[p] = 0.0f;

        // prime the free barriers (both parities available)
        BARRV(BAR_FREE0, NTHR);
        BARRV(BAR_FREE1, NTHR);

        for (int t = 0; t < T_LEN; t++) {
            const int p = t & 1;
            const float* br = p ? bufB : bufA;  // h0[t]

            BSYNC(BAR_L1INT, 256);              // h1 writes of t-1 visible

            u64 aI[4], aF[4], aG[4], aO[4];
#pragma unroll
            for (int q = 0; q < 4; q++) { aI[q] = bi1; aF[q] = bf1; aG[q] = bg1; aO[q] = bo1; }

            gemv64(whh1, h1s, j, bb, aI, aF, aG, aO);   // recurrent part (h1[t-1])

            if (p) { BSYNC(BAR_READY1, NTHR); } else { BSYNC(BAR_READY0, NTHR); }

            gemv64(wih1, br, j, bb, aI, aF, aG, aO);    // input part (h0[t])

            if (p) { BARRV(BAR_FREE1, NTHR); } else { BARRV(BAR_FREE0, NTHR); }

            float hn[8];
            pointwise(aI, aF, aG, aO, c1, hn);
            // WAR on h1s: every L1 thread passed the ready-sync (group
            // rendezvous) after finishing its recurrent reads of h1s.
            *(float4*)&h1s[j * HS + bb]     = make_float4(hn[0], hn[1], hn[2], hn[3]);
            *(float4*)&h1s[j * HS + bb + 4] = make_float4(hn[4], hn[5], hn[6], hn[7]);
        }
    }
    __syncthreads();

    // ================= MLP head: out = W2 @ relu(W1 @ h2 + b1) + b2 =========
    if (tid < NB) {
        float acc = b2[0];
#pragma unroll 1
        for (int u = 0; u < 32; u++) {
            float s = b1[u];
            const float* wr = W1 + u * 64;
#pragma unroll
            for (int k = 0; k < 64; k++) s += wr[k] * h1s[k * HS + tid];
            acc += W2[u] * fmaxf(s, 0.0f);
        }
        out[B0 + tid] = acc;
    }
}

extern "C" void kernel_launch(void* const* d_in, const int* in_sizes, int n_in,
                              void* d_out, int out_size)
{
    const float* x    = (const float*)d_in[0];
    const float* Wih0 = (const float*)d_in[1];
    const float* Whh0 = (const float*)d_in[2];
    const float* bih0 = (const float*)d_in[3];
    const float* bhh0 = (const float*)d_in[4];
    const float* Wih1 = (const float*)d_in[5];
    const float* Whh1 = (const float*)d_in[6];
    const float* bih1 = (const float*)d_in[7];
    const float* bhh1 = (const float*)d_in[8];
    const float* W1   = (const float*)d_in[9];
    const float* b1   = (const float*)d_in[10];
    const float* W2   = (const float*)d_in[11];
    const float* b2   = (const float*)d_in[12];
    float* out = (float*)d_out;

    cudaFuncSetAttribute(stocklstm_kernel,
                         cudaFuncAttributeMaxDynamicSharedMemorySize, SMEM_BYTES);
    stocklstm_kernel<<<B_TOT / NB, NTHR, SMEM_BYTES>>>(
        x, Wih0, Whh0, bih0, bhh0, Wih1, Whh1, bih1, bhh1, W1, b1, W2, b2, out);
}